// round 16
// baseline (speedup 1.0000x reference)
#include <cuda_runtime.h>
#include <cuda_fp16.h>
#include <cstdint>

#define N_NODES 100000
#define FEAT    64
#define NF      (N_NODES * FEAT)
#define E_MAX   1700000
#define GRID    296            // 2 blocks/SM on 148 SMs (co-resident, barrier-safe)
#define TPB     512
#define CHUNK   338            // ceil(N_NODES / GRID)
#define NBAR    4
#define NTILES  (N_NODES / 16) // 6250 row-tiles of 16

// Scratch: device globals (no allocations allowed). Zero-initialized.
// g_cnt invariant: zero at entry to every launch (re-zeroed in phase 4).
__device__ __align__(16) __half2 g_uh[NF / 2];   // fp16 feature buffers
__device__ __align__(16) __half2 g_uh2[NF / 2];
__device__ int   g_cnt[N_NODES];
__device__ int   g_off[N_NODES + 1];
__device__ int   g_cur[N_NODES];
__device__ __align__(16) int g_adj[E_MAX];
__device__ int   g_blk[GRID];
__device__ float g_dinv[N_NODES];    // (deg)^{-1/2}, deg includes self-loop
__device__ float g_dinv2[N_NODES];   // (deg)^{-1}
// Grid barrier state; slot k's flag resets at release of slot k+1 (circular
// over NBAR used slots), so state self-cleans every launch (replay-safe).
__device__ unsigned      g_bar_cnt[NBAR];
__device__ volatile int  g_bar_flag[NBAR];

// ---------------------------------------------------------------------------
__device__ __forceinline__ void grid_barrier(int slot) {
    __syncthreads();
    if (threadIdx.x == 0) {
        __threadfence();
        unsigned old = atomicAdd(&g_bar_cnt[slot], 1u);
        if (old == GRID - 1) {
            g_bar_cnt[slot] = 0;
            g_bar_flag[(slot + NBAR - 1) % NBAR] = 0;
            __threadfence();
            g_bar_flag[slot] = 1;
        } else {
            while (g_bar_flag[slot] == 0) { __nanosleep(64); }
            __threadfence();
        }
    }
    __syncthreads();
}

__device__ __forceinline__ int edge_idx(const void* ei, int E, int half, int e,
                                        int is64) {
    if (is64) return (int)((const long long*)ei)[(size_t)half * E + e];
    return ((const int*)ei)[(size_t)half * E + e];
}

__device__ __forceinline__ unsigned f2h2(float a, float b) {
    __half2 h = __floats2half2_rn(a, b);
    return *reinterpret_cast<unsigned*>(&h);
}
__device__ __forceinline__ float2 h2f2(unsigned u) {
    __half2 h = *reinterpret_cast<__half2*>(&u);
    return __half22float2(h);
}
__device__ __forceinline__ __half2 u2h(unsigned u) {
    return *reinterpret_cast<__half2*>(&u);
}

// ---------------------------------------------------------------------------
// Kernel 1: CSR build (hist, scan, scatter) + folded tensor-core GEMM.
__global__ void __launch_bounds__(TPB, 2)
sgc_build(const float* __restrict__ x, const void* __restrict__ ei, int E,
          const float* __restrict__ W) {
    __shared__ __align__(16) char s_mem[17472];   // Wh2 (GEMM) / bs (scan)
    int* bs = reinterpret_cast<int*>(s_mem);      // scan scratch (2048B)

    const int tid = threadIdx.x;
    const int bid = blockIdx.x;
    const int gthread = bid * TPB + tid;
    const int gstride = GRID * TPB;

    // ---- Block-local dtype detect (no grid dependency) ---------------------
    int any = 0;
    {
        const int* ei32 = (const int*)ei;
        for (int i = tid; i < 1024; i += TPB)
            any |= (ei32[2 * i + 1] != 0);
    }
    const int is64 = (__syncthreads_or(any) == 0);

    // ---- Phase 1: degree histogram (g_cnt is zero at entry) ----------------
    for (int e = gthread; e < E; e += gstride) {
        unsigned t = (unsigned)edge_idx(ei, E, 1, e, is64);
        if (t < N_NODES) atomicAdd(&g_cnt[t], 1);
    }
    grid_barrier(0);

    // ---- Phase 2: per-block chunk sums ------------------------------------
    {
        int beg = bid * CHUNK;
        int len = N_NODES - beg; if (len > CHUNK) len = CHUNK; if (len < 0) len = 0;
        int v = (tid < len) ? g_cnt[beg + tid] : 0;
        bs[tid] = v;
        __syncthreads();
        for (int off = TPB / 2; off > 0; off >>= 1) {
            if (tid < off) bs[tid] += bs[tid + off];
            __syncthreads();
        }
        if (tid == 0) g_blk[bid] = bs[0];
    }
    grid_barrier(1);

    // ---- Phase 3: block 0 scans the 296 block sums ------------------------
    if (bid == 0) {
        int v = (tid < GRID) ? g_blk[tid] : 0;
        bs[tid] = v;
        __syncthreads();
        for (int off = 1; off < TPB; off <<= 1) {    // Hillis-Steele inclusive
            int p = (tid >= off) ? bs[tid - off] : 0;
            __syncthreads();
            bs[tid] += p;
            __syncthreads();
        }
        if (tid < GRID) g_blk[tid] = bs[tid] - v;    // exclusive
        if (tid == 0) g_off[N_NODES] = bs[TPB - 1];
    }
    grid_barrier(2);

    // ---- Phase 4: per-chunk exclusive scan + dinv/dinv2 + g_cnt re-zero ----
    {
        int beg = bid * CHUNK;
        int len = N_NODES - beg; if (len > CHUNK) len = CHUNK; if (len < 0) len = 0;
        int c = (tid < len) ? g_cnt[beg + tid] : 0;
        bs[tid] = c;
        __syncthreads();
        for (int off = 1; off < TPB; off <<= 1) {
            int p = (tid >= off) ? bs[tid - off] : 0;
            __syncthreads();
            bs[tid] += p;
            __syncthreads();
        }
        if (tid < len) {
            int excl = g_blk[bid] + bs[tid] - c;
            int i = beg + tid;
            g_off[i] = excl;
            g_cur[i] = excl;
            g_cnt[i] = 0;                      // restore zero invariant
            float deg = (float)c + 1.0f;
            g_dinv[i]  = rsqrtf(deg);
            g_dinv2[i] = 1.0f / deg;
        }
    }
    grid_barrier(3);

    // ---- Phase 5: scatter (CSR fill) then tensor-core GEMM ------------------
    for (int e = gthread; e < E; e += gstride) {
        unsigned t = (unsigned)edge_idx(ei, E, 1, e, is64);
        unsigned s = (unsigned)edge_idx(ei, E, 0, e, is64);
        if (t >= N_NODES || s >= N_NODES) continue;
        int pos = atomicAdd(&g_cur[t], 1);
        if (pos < E_MAX) g_adj[pos] = (int)s;
    }
    // GEMM: u0[i,:] = dinv[i] * (x[i,:] @ W^T), stored fp16.
    // HMMA m16n8k16: warp computes a 16x64 tile, fp32 accumulate.
    {
        __syncthreads();   // bs scratch -> Wh2 reuse
        __half2* Wh2 = reinterpret_cast<__half2*>(s_mem);   // [n][kp], stride 68
        for (int i = tid; i < 64 * 64; i += TPB) {          // 4096 W half2-pairs
            int n = i >> 6, kp = i & 63;
            float2 wv = __ldg(&reinterpret_cast<const float2*>(W)[(size_t)n * 64 + kp]);
            Wh2[n * 68 + kp] = __floats2half2_rn(wv.x, wv.y);
        }
        __syncthreads();

        const float2* x2 = reinterpret_cast<const float2*>(x);
        int lane = tid & 31;
        int wrp  = tid >> 5;
        int qp = lane >> 2;     // lane/4
        int rp = lane & 3;      // lane%4

        for (int tile = bid * 16 + wrp; tile < NTILES; tile += GRID * 16) {
            int r0 = tile * 16 + qp;     // this thread's rows: r0 and r0+8

            float acc[8][4];
            #pragma unroll
            for (int nt = 0; nt < 8; nt++)
                acc[nt][0] = acc[nt][1] = acc[nt][2] = acc[nt][3] = 0.f;

            #pragma unroll
            for (int ks = 0; ks < 8; ks++) {
                int kb = ks * 8 + rp;
                float2 va0 = __ldg(&x2[(size_t)r0 * 64 + kb]);
                float2 va1 = __ldg(&x2[(size_t)(r0 + 8) * 64 + kb]);
                float2 va2 = __ldg(&x2[(size_t)r0 * 64 + kb + 4]);
                float2 va3 = __ldg(&x2[(size_t)(r0 + 8) * 64 + kb + 4]);
                unsigned a0 = f2h2(va0.x, va0.y);
                unsigned a1 = f2h2(va1.x, va1.y);
                unsigned a2 = f2h2(va2.x, va2.y);
                unsigned a3 = f2h2(va3.x, va3.y);

                #pragma unroll
                for (int nt = 0; nt < 8; nt++) {
                    int col = nt * 8 + qp;
                    __half2 b0h = Wh2[col * 68 + ks * 8 + rp];
                    __half2 b1h = Wh2[col * 68 + ks * 8 + rp + 4];
                    unsigned b0 = *reinterpret_cast<unsigned*>(&b0h);
                    unsigned b1 = *reinterpret_cast<unsigned*>(&b1h);
                    asm volatile(
                        "mma.sync.aligned.m16n8k16.row.col.f32.f16.f16.f32 "
                        "{%0,%1,%2,%3}, {%4,%5,%6,%7}, {%8,%9}, {%0,%1,%2,%3};"
                        : "+f"(acc[nt][0]), "+f"(acc[nt][1]),
                          "+f"(acc[nt][2]), "+f"(acc[nt][3])
                        : "r"(a0), "r"(a1), "r"(a2), "r"(a3), "r"(b0), "r"(b1));
                }
            }

            float sc0 = g_dinv[r0];
            float sc1 = g_dinv[r0 + 8];
            #pragma unroll
            for (int nt = 0; nt < 8; nt++) {
                g_uh[(size_t)r0 * 32 + nt * 4 + rp] =
                    __floats2half2_rn(sc0 * acc[nt][0], sc0 * acc[nt][1]);
                g_uh[(size_t)(r0 + 8) * 32 + nt * 4 + rp] =
                    __floats2half2_rn(sc1 * acc[nt][2], sc1 * acc[nt][3]);
            }
        }
    }
}

// ---------------------------------------------------------------------------
// Kernels 2-4: gather hop. ONE WARP per node, two 16-lane halves own
// contiguous halves of the edge list. Lane hl owns features [4hl..4hl+3]
// (uint2 = 4 fp16). Main loop: one int4 load of 4 adjacency indices, 4
// independent gathers, two-level fp16 pairwise tree, fp32 accumulate.
template <int PASS>
__global__ void __launch_bounds__(256)
sgc_hop(float* __restrict__ outp, const float* __restrict__ b) {
    const uint2* uin = reinterpret_cast<const uint2*>((PASS == 1) ? g_uh2 : g_uh);
    uint2* uout = reinterpret_cast<uint2*>((PASS == 0) ? g_uh2 : g_uh);
    int lane = threadIdx.x & 31;
    int half = lane >> 4;
    unsigned hl = lane & 15;

    int node = blockIdx.x * 8 + (threadIdx.x >> 5);
    if (node >= N_NODES) return;

    int d   = g_off[node];
    int n   = g_off[node + 1] - d;
    int n0  = (n + 1) >> 1;              // half 0's share
    int beg = d + (half ? n0 : 0);
    int endc = beg + (half ? (n - n0) : n0);

    float4 s = make_float4(0.f, 0.f, 0.f, 0.f);
    if (half == 0) {                     // self-loop term counted once
        uint2 v = uin[(unsigned)node * 16u + hl];
        float2 f0 = h2f2(v.x), f1 = h2f2(v.y);
        s.x = f0.x; s.y = f0.y; s.z = f1.x; s.w = f1.y;
    }

    int i = beg;
    // scalar prologue to 16B-align the int4 adjacency loads
    for (; i < endc && (i & 3); i++) {
        unsigned j = (unsigned)__ldg(&g_adj[i]);
        uint2 v = __ldg(&uin[j * 16u + hl]);
        float2 f0 = h2f2(v.x), f1 = h2f2(v.y);
        s.x += f0.x; s.y += f0.y; s.z += f1.x; s.w += f1.y;
    }
    // vector main loop: 4 edges per iteration
    for (; i + 4 <= endc; i += 4) {
        int4 jj = *reinterpret_cast<const int4*>(&g_adj[i]);   // LDG.128
        uint2 v0 = __ldg(&uin[(unsigned)jj.x * 16u + hl]);
        uint2 v1 = __ldg(&uin[(unsigned)jj.y * 16u + hl]);
        uint2 v2 = __ldg(&uin[(unsigned)jj.z * 16u + hl]);
        uint2 v3 = __ldg(&uin[(unsigned)jj.w * 16u + hl]);
        __half2 p0 = __hadd2(u2h(v0.x), u2h(v1.x));   // level 1 (fp16)
        __half2 p1 = __hadd2(u2h(v0.y), u2h(v1.y));
        __half2 q0 = __hadd2(u2h(v2.x), u2h(v3.x));
        __half2 q1 = __hadd2(u2h(v2.y), u2h(v3.y));
        __half2 r0 = __hadd2(p0, q0);                 // level 2 (fp16)
        __half2 r1 = __hadd2(p1, q1);
        float2 f0 = __half22float2(r0);
        float2 f1 = __half22float2(r1);
        s.x += f0.x; s.y += f0.y; s.z += f1.x; s.w += f1.y;
    }
    // scalar tail
    for (; i < endc; i++) {
        unsigned j = (unsigned)__ldg(&g_adj[i]);
        uint2 v = __ldg(&uin[j * 16u + hl]);
        float2 f0 = h2f2(v.x), f1 = h2f2(v.y);
        s.x += f0.x; s.y += f0.y; s.z += f1.x; s.w += f1.y;
    }

    // combine halves
    s.x += __shfl_xor_sync(0xFFFFFFFFu, s.x, 16);
    s.y += __shfl_xor_sync(0xFFFFFFFFu, s.y, 16);
    s.z += __shfl_xor_sync(0xFFFFFFFFu, s.z, 16);
    s.w += __shfl_xor_sync(0xFFFFFFFFu, s.w, 16);

    if (half == 0) {
        if (PASS == 2) {
            float sc = g_dinv[node];
            float4 bb = __ldg(&reinterpret_cast<const float4*>(b)[hl]);
            float4 o;
            o.x = sc * s.x + bb.x;
            o.y = sc * s.y + bb.y;
            o.z = sc * s.z + bb.z;
            o.w = sc * s.w + bb.w;
            reinterpret_cast<float4*>(outp)[(unsigned)node * 16u + hl] = o;
        } else {
            float sc = g_dinv2[node];
            uint2 o;
            o.x = f2h2(sc * s.x, sc * s.y);
            o.y = f2h2(sc * s.z, sc * s.w);
            uout[(unsigned)node * 16u + hl] = o;
        }
    }
}

// ---------------------------------------------------------------------------
extern "C" void kernel_launch(void* const* d_in, const int* in_sizes, int n_in,
                              void* d_out, int out_size) {
    const float* x  = (const float*)d_in[0];   // [100000,128]
    const void*  ei = d_in[1];                 // [2, E] int32 or int64
    const float* W  = (const float*)d_in[2];   // [64,128]
    const float* b  = (const float*)d_in[3];   // [64]
    float* out = (float*)d_out;

    const int E = in_sizes[1] / 2;             // 1,600,000

    sgc_build<<<GRID, TPB>>>(x, ei, E, W);

    const int hb = (N_NODES + 7) / 8;          // warp-per-node, 8 warps/block
    sgc_hop<0><<<hb, 256>>>(nullptr, b);
    sgc_hop<1><<<hb, 256>>>(nullptr, b);
    sgc_hop<2><<<hb, 256>>>(out, b);
}

// round 17
// speedup vs baseline: 1.2452x; 1.2452x over previous
#include <cuda_runtime.h>
#include <cuda_fp16.h>
#include <cstdint>

#define N_NODES 100000
#define FEAT    64
#define NF      (N_NODES * FEAT)
#define E_MAX   1700000
#define GRID    296            // 2 blocks/SM on 148 SMs (co-resident, barrier-safe)
#define TPB     512
#define CHUNK   338            // ceil(N_NODES / GRID)
#define NBAR    4
#define NTILES  (N_NODES / 16) // 6250 row-tiles of 16

// Scratch: device globals (no allocations allowed). Zero-initialized.
// g_cnt invariant: zero at entry to every launch (re-zeroed in phase 4).
__device__ __align__(16) __half2 g_uh[NF / 2];   // fp16 feature buffers
__device__ __align__(16) __half2 g_uh2[NF / 2];
__device__ int   g_cnt[N_NODES];
__device__ int   g_off[N_NODES + 1];
__device__ int   g_cur[N_NODES];
__device__ __align__(16) int g_adj[E_MAX];
__device__ int   g_blk[GRID];
__device__ float g_dinv[N_NODES];    // (deg)^{-1/2}, deg includes self-loop
__device__ float g_dinv2[N_NODES];   // (deg)^{-1}
// Grid barrier state; slot k's flag resets at release of slot k+1 (circular
// over NBAR used slots), so state self-cleans every launch (replay-safe).
__device__ unsigned      g_bar_cnt[NBAR];
__device__ volatile int  g_bar_flag[NBAR];

// ---------------------------------------------------------------------------
__device__ __forceinline__ void grid_barrier(int slot) {
    __syncthreads();
    if (threadIdx.x == 0) {
        __threadfence();
        unsigned old = atomicAdd(&g_bar_cnt[slot], 1u);
        if (old == GRID - 1) {
            g_bar_cnt[slot] = 0;
            g_bar_flag[(slot + NBAR - 1) % NBAR] = 0;
            __threadfence();
            g_bar_flag[slot] = 1;
        } else {
            while (g_bar_flag[slot] == 0) { __nanosleep(64); }
            __threadfence();
        }
    }
    __syncthreads();
}

__device__ __forceinline__ int edge_idx(const void* ei, int E, int half, int e,
                                        int is64) {
    if (is64) return (int)((const long long*)ei)[(size_t)half * E + e];
    return ((const int*)ei)[(size_t)half * E + e];
}

__device__ __forceinline__ unsigned f2h2(float a, float b) {
    __half2 h = __floats2half2_rn(a, b);
    return *reinterpret_cast<unsigned*>(&h);
}
__device__ __forceinline__ float2 h2f2(unsigned u) {
    __half2 h = *reinterpret_cast<__half2*>(&u);
    return __half22float2(h);
}
__device__ __forceinline__ __half2 u2h(unsigned u) {
    return *reinterpret_cast<__half2*>(&u);
}

// ---------------------------------------------------------------------------
// Kernel 1: CSR build (hist, scan, scatter) + folded tensor-core GEMM.
__global__ void __launch_bounds__(TPB, 2)
sgc_build(const float* __restrict__ x, const void* __restrict__ ei, int E,
          const float* __restrict__ W) {
    __shared__ __align__(16) char s_mem[17472];   // Wh2 (GEMM) / bs (scan)
    int* bs = reinterpret_cast<int*>(s_mem);      // scan scratch (2048B)

    const int tid = threadIdx.x;
    const int bid = blockIdx.x;
    const int gthread = bid * TPB + tid;
    const int gstride = GRID * TPB;

    // ---- Block-local dtype detect (no grid dependency) ---------------------
    int any = 0;
    {
        const int* ei32 = (const int*)ei;
        for (int i = tid; i < 1024; i += TPB)
            any |= (ei32[2 * i + 1] != 0);
    }
    const int is64 = (__syncthreads_or(any) == 0);

    // ---- Phase 1: degree histogram (g_cnt is zero at entry) ----------------
    for (int e = gthread; e < E; e += gstride) {
        unsigned t = (unsigned)edge_idx(ei, E, 1, e, is64);
        if (t < N_NODES) atomicAdd(&g_cnt[t], 1);
    }
    grid_barrier(0);

    // ---- Phase 2: per-block chunk sums ------------------------------------
    {
        int beg = bid * CHUNK;
        int len = N_NODES - beg; if (len > CHUNK) len = CHUNK; if (len < 0) len = 0;
        int v = (tid < len) ? g_cnt[beg + tid] : 0;
        bs[tid] = v;
        __syncthreads();
        for (int off = TPB / 2; off > 0; off >>= 1) {
            if (tid < off) bs[tid] += bs[tid + off];
            __syncthreads();
        }
        if (tid == 0) g_blk[bid] = bs[0];
    }
    grid_barrier(1);

    // ---- Phase 3: block 0 scans the 296 block sums ------------------------
    if (bid == 0) {
        int v = (tid < GRID) ? g_blk[tid] : 0;
        bs[tid] = v;
        __syncthreads();
        for (int off = 1; off < TPB; off <<= 1) {    // Hillis-Steele inclusive
            int p = (tid >= off) ? bs[tid - off] : 0;
            __syncthreads();
            bs[tid] += p;
            __syncthreads();
        }
        if (tid < GRID) g_blk[tid] = bs[tid] - v;    // exclusive
        if (tid == 0) g_off[N_NODES] = bs[TPB - 1];
    }
    grid_barrier(2);

    // ---- Phase 4: per-chunk exclusive scan + dinv/dinv2 + g_cnt re-zero ----
    {
        int beg = bid * CHUNK;
        int len = N_NODES - beg; if (len > CHUNK) len = CHUNK; if (len < 0) len = 0;
        int c = (tid < len) ? g_cnt[beg + tid] : 0;
        bs[tid] = c;
        __syncthreads();
        for (int off = 1; off < TPB; off <<= 1) {
            int p = (tid >= off) ? bs[tid - off] : 0;
            __syncthreads();
            bs[tid] += p;
            __syncthreads();
        }
        if (tid < len) {
            int excl = g_blk[bid] + bs[tid] - c;
            int i = beg + tid;
            g_off[i] = excl;
            g_cur[i] = excl;
            g_cnt[i] = 0;                      // restore zero invariant
            float deg = (float)c + 1.0f;
            g_dinv[i]  = rsqrtf(deg);
            g_dinv2[i] = 1.0f / deg;
        }
    }
    grid_barrier(3);

    // ---- Phase 5: scatter (CSR fill) then tensor-core GEMM ------------------
    for (int e = gthread; e < E; e += gstride) {
        unsigned t = (unsigned)edge_idx(ei, E, 1, e, is64);
        unsigned s = (unsigned)edge_idx(ei, E, 0, e, is64);
        if (t >= N_NODES || s >= N_NODES) continue;
        int pos = atomicAdd(&g_cur[t], 1);
        if (pos < E_MAX) g_adj[pos] = (int)s;
    }
    // GEMM: u0[i,:] = dinv[i] * (x[i,:] @ W^T), stored fp16.
    // HMMA m16n8k16: warp computes a 16x64 tile, fp32 accumulate.
    {
        __syncthreads();   // bs scratch -> Wh2 reuse
        __half2* Wh2 = reinterpret_cast<__half2*>(s_mem);   // [n][kp], stride 68
        for (int i = tid; i < 64 * 64; i += TPB) {          // 4096 W half2-pairs
            int n = i >> 6, kp = i & 63;
            float2 wv = __ldg(&reinterpret_cast<const float2*>(W)[(size_t)n * 64 + kp]);
            Wh2[n * 68 + kp] = __floats2half2_rn(wv.x, wv.y);
        }
        __syncthreads();

        const float2* x2 = reinterpret_cast<const float2*>(x);
        int lane = tid & 31;
        int wrp  = tid >> 5;
        int qp = lane >> 2;     // lane/4
        int rp = lane & 3;      // lane%4

        for (int tile = bid * 16 + wrp; tile < NTILES; tile += GRID * 16) {
            int r0 = tile * 16 + qp;     // this thread's rows: r0 and r0+8

            float acc[8][4];
            #pragma unroll
            for (int nt = 0; nt < 8; nt++)
                acc[nt][0] = acc[nt][1] = acc[nt][2] = acc[nt][3] = 0.f;

            #pragma unroll
            for (int ks = 0; ks < 8; ks++) {
                int kb = ks * 8 + rp;
                float2 va0 = __ldg(&x2[(size_t)r0 * 64 + kb]);
                float2 va1 = __ldg(&x2[(size_t)(r0 + 8) * 64 + kb]);
                float2 va2 = __ldg(&x2[(size_t)r0 * 64 + kb + 4]);
                float2 va3 = __ldg(&x2[(size_t)(r0 + 8) * 64 + kb + 4]);
                unsigned a0 = f2h2(va0.x, va0.y);
                unsigned a1 = f2h2(va1.x, va1.y);
                unsigned a2 = f2h2(va2.x, va2.y);
                unsigned a3 = f2h2(va3.x, va3.y);

                #pragma unroll
                for (int nt = 0; nt < 8; nt++) {
                    int col = nt * 8 + qp;
                    __half2 b0h = Wh2[col * 68 + ks * 8 + rp];
                    __half2 b1h = Wh2[col * 68 + ks * 8 + rp + 4];
                    unsigned b0 = *reinterpret_cast<unsigned*>(&b0h);
                    unsigned b1 = *reinterpret_cast<unsigned*>(&b1h);
                    asm volatile(
                        "mma.sync.aligned.m16n8k16.row.col.f32.f16.f16.f32 "
                        "{%0,%1,%2,%3}, {%4,%5,%6,%7}, {%8,%9}, {%0,%1,%2,%3};"
                        : "+f"(acc[nt][0]), "+f"(acc[nt][1]),
                          "+f"(acc[nt][2]), "+f"(acc[nt][3])
                        : "r"(a0), "r"(a1), "r"(a2), "r"(a3), "r"(b0), "r"(b1));
                }
            }

            float sc0 = g_dinv[r0];
            float sc1 = g_dinv[r0 + 8];
            #pragma unroll
            for (int nt = 0; nt < 8; nt++) {
                g_uh[(size_t)r0 * 32 + nt * 4 + rp] =
                    __floats2half2_rn(sc0 * acc[nt][0], sc0 * acc[nt][1]);
                g_uh[(size_t)(r0 + 8) * 32 + nt * 4 + rp] =
                    __floats2half2_rn(sc1 * acc[nt][2], sc1 * acc[nt][3]);
            }
        }
    }
}

// ---------------------------------------------------------------------------
// Kernels 2-4: gather hop (R15 structure; occupancy pinned to 8 blocks/SM).
// ONE WARP per node, two 16-lane halves own contiguous halves of the edge
// list. Lane hl owns features [4hl..4hl+3] (uint2 = 4 fp16). 4 edges per
// half per iteration, fp16 pairwise pre-sum then fp32 accumulation;
// shfl_xor(16) combines halves.
template <int PASS>
__global__ void __launch_bounds__(256, 8)
sgc_hop(float* __restrict__ outp, const float* __restrict__ b) {
    const uint2* uin = reinterpret_cast<const uint2*>((PASS == 1) ? g_uh2 : g_uh);
    uint2* uout = reinterpret_cast<uint2*>((PASS == 0) ? g_uh2 : g_uh);
    int lane = threadIdx.x & 31;
    int half = lane >> 4;
    unsigned hl = lane & 15;

    int node = blockIdx.x * 8 + (threadIdx.x >> 5);
    if (node >= N_NODES) return;

    int d   = g_off[node];
    int n   = g_off[node + 1] - d;
    int n0  = (n + 1) >> 1;              // half 0's share
    int beg = d + (half ? n0 : 0);
    int cnt = half ? (n - n0) : n0;

    float4 s = make_float4(0.f, 0.f, 0.f, 0.f);
    if (half == 0) {                     // self-loop term counted once
        uint2 v = uin[(unsigned)node * 16u + hl];
        float2 f0 = h2f2(v.x), f1 = h2f2(v.y);
        s.x = f0.x; s.y = f0.y; s.z = f1.x; s.w = f1.y;
    }

    int i = beg;
    int end4 = beg + (cnt & ~3);
    for (; i < end4; i += 4) {           // 4 edges per half per iter
        unsigned j0 = (unsigned)__ldg(&g_adj[i + 0]);
        unsigned j1 = (unsigned)__ldg(&g_adj[i + 1]);
        unsigned j2 = (unsigned)__ldg(&g_adj[i + 2]);
        unsigned j3 = (unsigned)__ldg(&g_adj[i + 3]);
        uint2 v0 = __ldg(&uin[j0 * 16u + hl]);
        uint2 v1 = __ldg(&uin[j1 * 16u + hl]);
        uint2 v2 = __ldg(&uin[j2 * 16u + hl]);
        uint2 v3 = __ldg(&uin[j3 * 16u + hl]);
        __half2 p0 = __hadd2(u2h(v0.x), u2h(v1.x));   // fp16 pairwise
        __half2 p1 = __hadd2(u2h(v0.y), u2h(v1.y));
        __half2 q0 = __hadd2(u2h(v2.x), u2h(v3.x));
        __half2 q1 = __hadd2(u2h(v2.y), u2h(v3.y));
        float2 f0 = __half22float2(p0);
        float2 f1 = __half22float2(p1);
        float2 g0 = __half22float2(q0);
        float2 g1 = __half22float2(q1);
        s.x += f0.x + g0.x;  s.y += f0.y + g0.y;
        s.z += f1.x + g1.x;  s.w += f1.y + g1.y;
    }
    int endc = beg + cnt;
    for (; i < endc; i++) {              // 0..3 leftovers (exact fp32 add)
        unsigned j = (unsigned)__ldg(&g_adj[i]);
        uint2 v = __ldg(&uin[j * 16u + hl]);
        float2 f0 = h2f2(v.x), f1 = h2f2(v.y);
        s.x += f0.x; s.y += f0.y; s.z += f1.x; s.w += f1.y;
    }

    // combine halves
    s.x += __shfl_xor_sync(0xFFFFFFFFu, s.x, 16);
    s.y += __shfl_xor_sync(0xFFFFFFFFu, s.y, 16);
    s.z += __shfl_xor_sync(0xFFFFFFFFu, s.z, 16);
    s.w += __shfl_xor_sync(0xFFFFFFFFu, s.w, 16);

    if (half == 0) {
        if (PASS == 2) {
            float sc = g_dinv[node];
            float4 bb = __ldg(&reinterpret_cast<const float4*>(b)[hl]);
            float4 o;
            o.x = sc * s.x + bb.x;
            o.y = sc * s.y + bb.y;
            o.z = sc * s.z + bb.z;
            o.w = sc * s.w + bb.w;
            reinterpret_cast<float4*>(outp)[(unsigned)node * 16u + hl] = o;
        } else {
            float sc = g_dinv2[node];
            uint2 o;
            o.x = f2h2(sc * s.x, sc * s.y);
            o.y = f2h2(sc * s.z, sc * s.w);
            uout[(unsigned)node * 16u + hl] = o;
        }
    }
}

// ---------------------------------------------------------------------------
extern "C" void kernel_launch(void* const* d_in, const int* in_sizes, int n_in,
                              void* d_out, int out_size) {
    const float* x  = (const float*)d_in[0];   // [100000,128]
    const void*  ei = d_in[1];                 // [2, E] int32 or int64
    const float* W  = (const float*)d_in[2];   // [64,128]
    const float* b  = (const float*)d_in[3];   // [64]
    float* out = (float*)d_out;

    const int E = in_sizes[1] / 2;             // 1,600,000

    sgc_build<<<GRID, TPB>>>(x, ei, E, W);

    const int hb = (N_NODES + 7) / 8;          // warp-per-node, 8 warps/block
    sgc_hop<0><<<hb, 256>>>(nullptr, b);
    sgc_hop<1><<<hb, 256>>>(nullptr, b);
    sgc_hop<2><<<hb, 256>>>(out, b);
}